// round 16
// baseline (speedup 1.0000x reference)
#include <cuda_runtime.h>
#include <cuda_fp16.h>
#include <math.h>
#include <mma.h>

namespace wm = nvcuda::wmma;

#define N_NODES 50000
#define NE      1600000
#define HH      4
#define CC      32
#define FF      128                // HH*CC
#define NEG_SLOPE 0.2f
#define SCAN_BLOCKS 13             // ceil(50000 / 4096)
#define NODE_BLOCKS 6250           // 50000 warps / 8 warps-per-block
#define DEG_BLOCKS  6250           // 1.6M threads / 256
#define EDGE_BLOCKS 6250           // 1.6M / 256

// ---------------- scratch (device globals; no allocations allowed) ----------------
__device__ __align__(16) __half g_xph[N_NODES * FF];    // projected features fp16 [N,128]
__device__ __align__(16) float  g_asrc[N_NODES * 4];
__device__ __align__(16) float  g_adst[N_NODES * 4];
__device__ __align__(16) int    g_deg[N_NODES];
__device__ __align__(16) int    g_rowptr[N_NODES + 4];
__device__ __align__(16) int    g_wptr[N_NODES + 4];
__device__ __align__(16) int4   g_rec[NE];              // {src, ah01(h2), ah23(h2), 0}
__device__ __align__(16) float  g_h[N_NODES * FF];      // ELU(out+bias) hidden
__device__ float  g_M[7 * 4];                           // folded edge attention matrix
__device__ unsigned g_scanstate[SCAN_BLOCKS];
__device__ int      g_scandone;

__device__ __forceinline__ float lrelu(float v) { return v > 0.f ? v : NEG_SLOPE * v; }

// ---------------- K0: zero counters + fold M ----------------
__global__ void k_init(const float* __restrict__ W_edge, const float* __restrict__ att_edge) {
    int t = blockIdx.x * blockDim.x + threadIdx.x;
    if (t < N_NODES) g_deg[t] = 0;
    if (blockIdx.x == 0) {
        int tt = threadIdx.x;
        if (tt < SCAN_BLOCKS) g_scanstate[tt] = 0u;
        if (tt == SCAN_BLOCKS) g_scandone = 0;
        if (tt < 28) {
            int k = tt >> 2, h = tt & 3;
            float s = 0.f;
            for (int c = 0; c < CC; c++) s += W_edge[k * FF + h * CC + c] * att_edge[h * CC + c];
            g_M[k * 4 + h] = s;
        }
    }
}

// ---------------- K1: fused node projection + degree count ----------------
__global__ void k_node_deg(const float* __restrict__ x, const float* __restrict__ W_gat,
                           const float* __restrict__ att_src, const float* __restrict__ att_dst,
                           const int* __restrict__ ei) {
    if (blockIdx.x >= NODE_BLOCKS) {
        int e = (blockIdx.x - NODE_BLOCKS) * blockDim.x + threadIdx.x;
        if (e < NE) atomicAdd(&g_deg[ei[NE + e]], 1);
        return;
    }
    int warp = (blockIdx.x * blockDim.x + threadIdx.x) >> 5;
    int lane = threadIdx.x & 31;
    if (warp >= N_NODES) return;
    int n = warp;
    float x0 = x[n * 3 + 0], x1 = x[n * 3 + 1], x2 = x[n * 3 + 2];
    int i0 = lane * 4;
    float v[4];
    float as = 0.f, ad = 0.f;
#pragma unroll
    for (int j = 0; j < 4; j++) {
        int i = i0 + j;
        float p = fmaf(x0, W_gat[i], fmaf(x1, W_gat[FF + i], x2 * W_gat[2 * FF + i]));
        v[j] = p;
        as = fmaf(p, att_src[i], as);
        ad = fmaf(p, att_dst[i], ad);
    }
    __half2 h0 = __floats2half2_rn(v[0], v[1]);
    __half2 h1 = __floats2half2_rn(v[2], v[3]);
    uint2 u;
    u.x = *(unsigned*)&h0;
    u.y = *(unsigned*)&h1;
    *(uint2*)&g_xph[n * FF + i0] = u;
#pragma unroll
    for (int o = 1; o < 8; o <<= 1) {
        as += __shfl_xor_sync(0xFFFFFFFFu, as, o);
        ad += __shfl_xor_sync(0xFFFFFFFFu, ad, o);
    }
    int h = lane >> 3;
    if ((lane & 7) == 0) {
        g_asrc[n * 4 + h] = as;
        g_adst[n * 4 + h] = ad;
    }
}

// ---------------- K2: fused {decoupled-lookback scan} + {per-edge fold + CSR scatter} ----------------
__global__ void k_edge(const int* __restrict__ ei, const float* __restrict__ ea) {
    int bid = blockIdx.x;
    int t = threadIdx.x, lane = t & 31, w = t >> 5;

    if (bid < SCAN_BLOCKS) {
        // ---- scan phase: 256 threads x 16 values = 4096 per block ----
        __shared__ int wsum[8];
        __shared__ int s_prefix;
        int base_i = bid * 4096 + t * 16;
        int vals[16];
        int tsum = 0;
#pragma unroll
        for (int q = 0; q < 4; q++) {
            int idx = base_i + q * 4;
            int4 d = (idx < N_NODES) ? *(const int4*)&g_deg[idx] : make_int4(0, 0, 0, 0);
            vals[q * 4 + 0] = d.x; vals[q * 4 + 1] = d.y;
            vals[q * 4 + 2] = d.z; vals[q * 4 + 3] = d.w;
            tsum += d.x + d.y + d.z + d.w;
        }
        int s = tsum;
#pragma unroll
        for (int o = 1; o < 32; o <<= 1) {
            int u = __shfl_up_sync(0xFFFFFFFFu, s, o);
            if (lane >= o) s += u;
        }
        if (lane == 31) wsum[w] = s;
        __syncthreads();
        if (w == 0 && lane < 8) {
            int ws = wsum[lane];
#pragma unroll
            for (int o = 1; o < 8; o <<= 1) {
                int u = __shfl_up_sync(0xFFu, ws, o);
                if (lane >= o) ws += u;
            }
            wsum[lane] = ws;
        }
        __syncthreads();
        int excl = (w > 0 ? wsum[w - 1] : 0) + s - tsum;
        int agg = wsum[7];
        if (t == 0) {
            unsigned pub = (bid == 0) ? (0x80000000u | (unsigned)agg) : (0x40000000u | (unsigned)agg);
            atomicExch(&g_scanstate[bid], pub);
            int prefix = 0;
            if (bid > 0) {
                for (int j = bid - 1; j >= 0; ) {
                    unsigned st;
                    do { st = atomicAdd(&g_scanstate[j], 0u); } while (st == 0u);
                    prefix += (int)(st & 0x3FFFFFFFu);
                    if (st & 0x80000000u) break;
                    j--;
                }
                atomicExch(&g_scanstate[bid], 0x80000000u | (unsigned)(prefix + agg));
            }
            s_prefix = prefix;
            if (bid == SCAN_BLOCKS - 1) g_rowptr[N_NODES] = prefix + agg;
        }
        __syncthreads();
        int run = s_prefix + excl;
#pragma unroll
        for (int q = 0; q < 4; q++) {
            int idx = base_i + q * 4;
            if (idx < N_NODES) {
                int4 r;
                r.x = run;
                r.y = run + vals[q * 4 + 0];
                r.z = r.y + vals[q * 4 + 1];
                r.w = r.z + vals[q * 4 + 2];
                *(int4*)&g_rowptr[idx] = r;
                *(int4*)&g_wptr[idx] = r;
                run = r.w + vals[q * 4 + 3];
            }
        }
        __threadfence();
        __syncthreads();
        if (t == 0) atomicAdd(&g_scandone, 1);
    }

    // ---- all blocks: wait for scan completion ----
    if (t == 0) {
        while (atomicAdd(&g_scandone, 0) < SCAN_BLOCKS) { }
    }
    __syncthreads();
    __threadfence();

    // ---- edge phase: fold ea, scatter record ----
    int e = bid * 256 + t;        // EDGE_BLOCKS*256 == NE exactly
    int src = ei[e];
    int dst = ei[NE + e];
    float ev[7];
#pragma unroll
    for (int k = 0; k < 7; k++) ev[k] = ea[e * 7 + k];
    float ah[4];
#pragma unroll
    for (int h = 0; h < 4; h++) {
        float s = 0.f;
#pragma unroll
        for (int k = 0; k < 7; k++) s = fmaf(ev[k], g_M[k * 4 + h], s);
        ah[h] = s;
    }
    __half2 a01 = __floats2half2_rn(ah[0], ah[1]);
    __half2 a23 = __floats2half2_rn(ah[2], ah[3]);
    int4 rec;
    rec.x = src;
    rec.y = *(int*)&a01;
    rec.z = *(int*)&a23;
    rec.w = 0;
    int pos = atomicAdd(&g_wptr[dst], 1);
    g_rec[pos] = rec;
}

// ---------------- K3: softmax + aggregation; alpha recomputed from record ----------------
__global__ void k_agg(const float* __restrict__ bias) {
    int warp = (blockIdx.x * blockDim.x + threadIdx.x) >> 5;
    int lane = threadIdx.x & 31;
    if (warp >= N_NODES) return;
    int n = warp;
    int rs = g_rowptr[n], re = g_rowptr[n + 1];
    int deg = re - rs;

    // pass 1: aesum (coalesced sweep of own records)
    float ae0 = 0.f, ae1 = 0.f, ae2 = 0.f, ae3 = 0.f;
    for (int i = rs + lane; i < re; i += 32) {
        int4 r = g_rec[i];
        float2 f01 = __half22float2(*(__half2*)&r.y);
        float2 f23 = __half22float2(*(__half2*)&r.z);
        ae0 += f01.x; ae1 += f01.y; ae2 += f23.x; ae3 += f23.y;
    }
#pragma unroll
    for (int o = 16; o > 0; o >>= 1) {
        ae0 += __shfl_xor_sync(0xFFFFFFFFu, ae0, o);
        ae1 += __shfl_xor_sync(0xFFFFFFFFu, ae1, o);
        ae2 += __shfl_xor_sync(0xFFFFFFFFu, ae2, o);
        ae3 += __shfl_xor_sync(0xFFFFFFFFu, ae3, o);
    }

    float4 as4 = *(const float4*)&g_asrc[n * 4];
    float4 ad4 = *(const float4*)&g_adst[n * 4];
    float invd = 1.0f / fmaxf((float)deg, 1.0f);
    float4 asl;
    asl.x = lrelu(as4.x + ad4.x + ae0 * invd);
    asl.y = lrelu(as4.y + ad4.y + ae1 * invd);
    asl.z = lrelu(as4.z + ad4.z + ae2 * invd);
    asl.w = lrelu(as4.w + ad4.w + ae3 * invd);

    int h = lane >> 3;
    float aslh  = (h == 0) ? asl.x : (h == 1) ? asl.y : (h == 2) ? asl.z : asl.w;
    float adsth = (h == 0) ? ad4.x : (h == 1) ? ad4.y : (h == 2) ? ad4.z : ad4.w;

    // seed with self-loop: weight exp(aslh - aslh) = 1
    float dh = 1.0f;
    float4 acc;
    {
        uint2 u = *(const uint2*)&g_xph[n * FF + lane * 4];
        float2 f01 = __half22float2(*(__half2*)&u.x);
        float2 f23 = __half22float2(*(__half2*)&u.y);
        acc = make_float4(f01.x, f01.y, f23.x, f23.y);
    }

    // pass 2: weights + gather, 8 edges in flight
    int i = rs;
    for (; i + 8 <= re; i += 8) {
        int s[8];
        float ahh[8];
        uint2 u[8];
#pragma unroll
        for (int j = 0; j < 8; j++) {
            int4 r = g_rec[i + j];           // broadcast across warp
            s[j] = r.x;
            float2 f01 = __half22float2(*(__half2*)&r.y);
            float2 f23 = __half22float2(*(__half2*)&r.z);
            ahh[j] = (h == 0) ? f01.x : (h == 1) ? f01.y : (h == 2) ? f23.x : f23.y;
        }
#pragma unroll
        for (int j = 0; j < 8; j++) u[j] = *(const uint2*)&g_xph[s[j] * FF + lane * 4];
#pragma unroll
        for (int j = 0; j < 8; j++) {
            float asrch = g_asrc[s[j] * 4 + h];          // 1-sector broadcast line
            float alpha = lrelu(asrch + adsth + ahh[j]);
            float wgt = __expf(alpha - aslh);
            dh += wgt;
            float2 f01 = __half22float2(*(__half2*)&u[j].x);
            float2 f23 = __half22float2(*(__half2*)&u[j].y);
            acc.x += wgt * f01.x; acc.y += wgt * f01.y;
            acc.z += wgt * f23.x; acc.w += wgt * f23.y;
        }
    }
    for (; i < re; i++) {
        int4 r = g_rec[i];
        float2 f01 = __half22float2(*(__half2*)&r.y);
        float2 f23 = __half22float2(*(__half2*)&r.z);
        float ahh = (h == 0) ? f01.x : (h == 1) ? f01.y : (h == 2) ? f23.x : f23.y;
        float asrch = g_asrc[r.x * 4 + h];
        float alpha = lrelu(asrch + adsth + ahh);
        float wgt = __expf(alpha - aslh);
        dh += wgt;
        uint2 u0 = *(const uint2*)&g_xph[r.x * FF + lane * 4];
        float2 g01 = __half22float2(*(__half2*)&u0.x), g23 = __half22float2(*(__half2*)&u0.y);
        acc.x += wgt * g01.x; acc.y += wgt * g01.y;
        acc.z += wgt * g23.x; acc.w += wgt * g23.y;
    }
    float ih = 1.0f / dh;

    // ELU(out + bias)
    float4 b = *(const float4*)&bias[lane * 4];
    float r0 = acc.x * ih + b.x, r1 = acc.y * ih + b.y;
    float r2 = acc.z * ih + b.z, r3 = acc.w * ih + b.w;
    r0 = r0 > 0.f ? r0 : expm1f(r0);
    r1 = r1 > 0.f ? r1 : expm1f(r1);
    r2 = r2 > 0.f ? r2 : expm1f(r2);
    r3 = r3 > 0.f ? r3 : expm1f(r3);
    *(float4*)&g_h[n * FF + lane * 4] = make_float4(r0, r1, r2, r3);
}

// ---------------- K4: fused MLP via tf32 tensor cores ----------------
// smem: sW1[128][128] + sW2[128][32] + shA[64][132] + sh1[64][132]
#define MLP_SMEM (16384*4 + 4096*4 + 8448*4 + 8448*4)
__global__ void k_mlp(const float* __restrict__ W1, const float* __restrict__ b1,
                      const float* __restrict__ pa, const float* __restrict__ W2,
                      const float* __restrict__ b2, float* __restrict__ out) {
    extern __shared__ float smem[];
    float* sW1 = smem;              // [128][128]
    float* sW2 = sW1 + 16384;       // [128][32]
    float* shA = sW2 + 4096;        // [64][132]  input h (then layer-2 output)
    float* sh1 = shA + 8448;        // [64][132]  hidden h1
    int t = threadIdx.x;
    int w = t >> 5;
    int m0 = blockIdx.x * 64;

    for (int i = t; i < 16384; i += 256) sW1[i] = W1[i];
    for (int i = t; i < 4096; i += 256)  sW2[i] = W2[i];
    for (int i = t; i < 64 * 128; i += 256) {
        int r = i >> 7, k = i & 127;
        int node = m0 + r;
        shA[r * 132 + k] = (node < N_NODES) ? g_h[node * 128 + k] : 0.f;
    }
    float prelu = pa[0];
    __syncthreads();

    // ---- layer 1: [64x128] @ [128x128]; 8 warps, each a 32x32 tile ----
    {
        int wr = w >> 2, wc = w & 3;
        wm::fragment<wm::accumulator, 16, 16, 8, float> acc[2][2];
#pragma unroll
        for (int i = 0; i < 2; i++)
#pragma unroll
            for (int j = 0; j < 2; j++) wm::fill_fragment(acc[i][j], 0.f);
        for (int k = 0; k < 128; k += 8) {
            wm::fragment<wm::matrix_a, 16, 16, 8, wm::precision::tf32, wm::row_major> a[2];
            wm::fragment<wm::matrix_b, 16, 16, 8, wm::precision::tf32, wm::row_major> b[2];
#pragma unroll
            for (int i = 0; i < 2; i++) {
                wm::load_matrix_sync(a[i], &shA[(wr * 32 + i * 16) * 132 + k], 132);
#pragma unroll
                for (int e = 0; e < a[i].num_elements; e++) a[i].x[e] = wm::__float_to_tf32(a[i].x[e]);
            }
#pragma unroll
            for (int j = 0; j < 2; j++) {
                wm::load_matrix_sync(b[j], &sW1[k * 128 + wc * 32 + j * 16], 128);
#pragma unroll
                for (int e = 0; e < b[j].num_elements; e++) b[j].x[e] = wm::__float_to_tf32(b[j].x[e]);
            }
#pragma unroll
            for (int i = 0; i < 2; i++)
#pragma unroll
                for (int j = 0; j < 2; j++)
                    wm::mma_sync(acc[i][j], a[i], b[j], acc[i][j]);
        }
#pragma unroll
        for (int i = 0; i < 2; i++)
#pragma unroll
            for (int j = 0; j < 2; j++)
                wm::store_matrix_sync(&sh1[(wr * 32 + i * 16) * 132 + wc * 32 + j * 16],
                                      acc[i][j], 132, wm::mem_row_major);
    }
    __syncthreads();
    // bias + PReLU in place
    for (int i = t; i < 64 * 128; i += 256) {
        int r = i >> 7, c = i & 127;
        float v = sh1[r * 132 + c] + b1[c];
        sh1[r * 132 + c] = v > 0.f ? v : prelu * v;
    }
    __syncthreads();
    // ---- layer 2: [64x128] @ [128x32]; 8 warps, each one 16x16 tile ----
    {
        int wr = w >> 1, wc = w & 1;
        wm::fragment<wm::accumulator, 16, 16, 8, float> acc;
        wm::fill_fragment(acc, 0.f);
        for (int k = 0; k < 128; k += 8) {
            wm::fragment<wm::matrix_a, 16, 16, 8, wm::precision::tf32, wm::row_major> a;
            wm::fragment<wm::matrix_b, 16, 16, 8, wm::precision::tf32, wm::row_major> b;
            wm::load_matrix_sync(a, &sh1[(wr * 16) * 132 + k], 132);
#pragma unroll
            for (int e = 0; e < a.num_elements; e++) a.x[e] = wm::__float_to_tf32(a.x[e]);
            wm::load_matrix_sync(b, &sW2[k * 32 + wc * 16], 32);
#pragma unroll
            for (int e = 0; e < b.num_elements; e++) b.x[e] = wm::__float_to_tf32(b.x[e]);
            wm::mma_sync(acc, a, b, acc);
        }
        wm::store_matrix_sync(&shA[(wr * 16) * 132 + wc * 16], acc, 132, wm::mem_row_major);
    }
    __syncthreads();
    // write out with b2
    for (int i = t; i < 64 * 32; i += 256) {
        int r = i >> 5, c = i & 31;
        int node = m0 + r;
        if (node < N_NODES) out[node * 32 + c] = shA[r * 132 + c] + b2[c];
    }
}

// ---------------- launch ----------------
extern "C" void kernel_launch(void* const* d_in, const int* in_sizes, int n_in,
                              void* d_out, int out_size) {
    const float*     x        = (const float*)d_in[0];
    const int*       ei       = (const int*)d_in[1];
    const float*     ea       = (const float*)d_in[2];
    const float*     W_gat    = (const float*)d_in[3];
    const float*     att_src  = (const float*)d_in[4];
    const float*     att_dst  = (const float*)d_in[5];
    const float*     W_edge   = (const float*)d_in[6];
    const float*     att_edge = (const float*)d_in[7];
    const float*     bias_gat = (const float*)d_in[8];
    const float*     W1       = (const float*)d_in[9];
    const float*     b1       = (const float*)d_in[10];
    const float*     prelu_a  = (const float*)d_in[11];
    const float*     W2       = (const float*)d_in[12];
    const float*     b2       = (const float*)d_in[13];
    float*           out      = (float*)d_out;

    cudaFuncSetAttribute(k_mlp, cudaFuncAttributeMaxDynamicSharedMemorySize, MLP_SMEM);

    k_init<<<(N_NODES + 255) / 256, 256>>>(W_edge, att_edge);
    k_node_deg<<<NODE_BLOCKS + DEG_BLOCKS, 256>>>(x, W_gat, att_src, att_dst, ei);
    k_edge<<<EDGE_BLOCKS, 256>>>(ei, ea);
    k_agg<<<(N_NODES * 32 + 255) / 256, 256>>>(bias_gat);
    k_mlp<<<(N_NODES + 63) / 64, 256, MLP_SMEM>>>(W1, b1, prelu_a, W2, b2, out);
}

// round 17
// speedup vs baseline: 1.1100x; 1.1100x over previous
#include <cuda_runtime.h>
#include <cuda_fp16.h>
#include <math.h>
#include <mma.h>

namespace wm = nvcuda::wmma;

#define N_NODES 50000
#define NE      1600000
#define HH      4
#define CC      32
#define FF      128                // HH*CC
#define NEG_SLOPE 0.2f
#define SCAN_BLOCKS 13             // ceil(50000 / 4096)
#define NODE_BLOCKS 6250           // 50000 warps / 8 warps-per-block
#define DEG_BLOCKS  6250           // 1.6M threads / 256
#define EDGE_BLOCKS 6250           // 1.6M / 256

// ---------------- scratch (device globals; no allocations allowed) ----------------
__device__ __align__(16) __half g_xph[N_NODES * FF];    // projected features fp16 [N,128]
__device__ __align__(16) float  g_asrc[N_NODES * 4];
__device__ __align__(16) float  g_adst[N_NODES * 4];
__device__ __align__(16) float  g_aesum[N_NODES * 4];   // folded edge-att segment sum (per head)
__device__ __align__(16) int    g_deg[N_NODES];
__device__ __align__(16) int    g_rowptr[N_NODES + 4];
__device__ __align__(16) int    g_wptr[N_NODES + 4];
__device__ int    g_csrc[NE];
__device__ float4 g_calpha[NE];
__device__ __align__(16) float  g_h[N_NODES * FF];      // ELU(out+bias) hidden
__device__ float  g_M[7 * 4];                           // folded edge attention matrix
__device__ unsigned g_scanstate[SCAN_BLOCKS];
__device__ int      g_scandone;

__device__ __forceinline__ float lrelu(float v) { return v > 0.f ? v : NEG_SLOPE * v; }

__device__ __forceinline__ void red_add_v4(float* p, float4 v) {
    asm volatile("red.global.add.v4.f32 [%0], {%1,%2,%3,%4};"
                 :: "l"(p), "f"(v.x), "f"(v.y), "f"(v.z), "f"(v.w) : "memory");
}

// ---------------- K0: zero counters + fold M ----------------
__global__ void k_init(const float* __restrict__ W_edge, const float* __restrict__ att_edge) {
    int t = blockIdx.x * blockDim.x + threadIdx.x;
    if (t < N_NODES) {
        g_deg[t] = 0;
        *(float4*)&g_aesum[t * 4] = make_float4(0.f, 0.f, 0.f, 0.f);
    }
    if (blockIdx.x == 0) {
        int tt = threadIdx.x;
        if (tt < SCAN_BLOCKS) g_scanstate[tt] = 0u;
        if (tt == SCAN_BLOCKS) g_scandone = 0;
        if (tt < 28) {
            int k = tt >> 2, h = tt & 3;
            float s = 0.f;
            for (int c = 0; c < CC; c++) s += W_edge[k * FF + h * CC + c] * att_edge[h * CC + c];
            g_M[k * 4 + h] = s;
        }
    }
}

// ---------------- K1: fused node projection + degree count ----------------
__global__ void k_node_deg(const float* __restrict__ x, const float* __restrict__ W_gat,
                           const float* __restrict__ att_src, const float* __restrict__ att_dst,
                           const int* __restrict__ ei) {
    if (blockIdx.x >= NODE_BLOCKS) {
        int e = (blockIdx.x - NODE_BLOCKS) * blockDim.x + threadIdx.x;
        if (e < NE) atomicAdd(&g_deg[ei[NE + e]], 1);
        return;
    }
    int warp = (blockIdx.x * blockDim.x + threadIdx.x) >> 5;
    int lane = threadIdx.x & 31;
    if (warp >= N_NODES) return;
    int n = warp;
    float x0 = x[n * 3 + 0], x1 = x[n * 3 + 1], x2 = x[n * 3 + 2];
    int i0 = lane * 4;
    float v[4];
    float as = 0.f, ad = 0.f;
#pragma unroll
    for (int j = 0; j < 4; j++) {
        int i = i0 + j;
        float p = fmaf(x0, W_gat[i], fmaf(x1, W_gat[FF + i], x2 * W_gat[2 * FF + i]));
        v[j] = p;
        as = fmaf(p, att_src[i], as);
        ad = fmaf(p, att_dst[i], ad);
    }
    __half2 h0 = __floats2half2_rn(v[0], v[1]);
    __half2 h1 = __floats2half2_rn(v[2], v[3]);
    uint2 u;
    u.x = *(unsigned*)&h0;
    u.y = *(unsigned*)&h1;
    *(uint2*)&g_xph[n * FF + i0] = u;
#pragma unroll
    for (int o = 1; o < 8; o <<= 1) {
        as += __shfl_xor_sync(0xFFFFFFFFu, as, o);
        ad += __shfl_xor_sync(0xFFFFFFFFu, ad, o);
    }
    int h = lane >> 3;
    if ((lane & 7) == 0) {
        g_asrc[n * 4 + h] = as;
        g_adst[n * 4 + h] = ad;
    }
}

// ---------------- K2: fused {decoupled-lookback scan} + {per-edge alpha + CSR scatter} ----------------
__global__ void k_edge(const int* __restrict__ ei, const float* __restrict__ ea) {
    int bid = blockIdx.x;
    int t = threadIdx.x, lane = t & 31, w = t >> 5;

    if (bid < SCAN_BLOCKS) {
        // ---- scan phase: 256 threads x 16 values = 4096 per block ----
        __shared__ int wsum[8];
        __shared__ int s_prefix;
        int base_i = bid * 4096 + t * 16;
        int vals[16];
        int tsum = 0;
#pragma unroll
        for (int q = 0; q < 4; q++) {
            int idx = base_i + q * 4;
            int4 d = (idx < N_NODES) ? *(const int4*)&g_deg[idx] : make_int4(0, 0, 0, 0);
            vals[q * 4 + 0] = d.x; vals[q * 4 + 1] = d.y;
            vals[q * 4 + 2] = d.z; vals[q * 4 + 3] = d.w;
            tsum += d.x + d.y + d.z + d.w;
        }
        int s = tsum;
#pragma unroll
        for (int o = 1; o < 32; o <<= 1) {
            int u = __shfl_up_sync(0xFFFFFFFFu, s, o);
            if (lane >= o) s += u;
        }
        if (lane == 31) wsum[w] = s;
        __syncthreads();
        if (w == 0 && lane < 8) {
            int ws = wsum[lane];
#pragma unroll
            for (int o = 1; o < 8; o <<= 1) {
                int u = __shfl_up_sync(0xFFu, ws, o);
                if (lane >= o) ws += u;
            }
            wsum[lane] = ws;
        }
        __syncthreads();
        int excl = (w > 0 ? wsum[w - 1] : 0) + s - tsum;
        int agg = wsum[7];
        if (t == 0) {
            unsigned pub = (bid == 0) ? (0x80000000u | (unsigned)agg) : (0x40000000u | (unsigned)agg);
            atomicExch(&g_scanstate[bid], pub);
            int prefix = 0;
            if (bid > 0) {
                for (int j = bid - 1; j >= 0; ) {
                    unsigned st;
                    do { st = atomicAdd(&g_scanstate[j], 0u); } while (st == 0u);
                    prefix += (int)(st & 0x3FFFFFFFu);
                    if (st & 0x80000000u) break;
                    j--;
                }
                atomicExch(&g_scanstate[bid], 0x80000000u | (unsigned)(prefix + agg));
            }
            s_prefix = prefix;
            if (bid == SCAN_BLOCKS - 1) g_rowptr[N_NODES] = prefix + agg;
        }
        __syncthreads();
        int run = s_prefix + excl;
#pragma unroll
        for (int q = 0; q < 4; q++) {
            int idx = base_i + q * 4;
            if (idx < N_NODES) {
                int4 r;
                r.x = run;
                r.y = run + vals[q * 4 + 0];
                r.z = r.y + vals[q * 4 + 1];
                r.w = r.z + vals[q * 4 + 2];
                *(int4*)&g_rowptr[idx] = r;
                *(int4*)&g_wptr[idx] = r;
                run = r.w + vals[q * 4 + 3];
            }
        }
        __threadfence();
        __syncthreads();
        if (t == 0) atomicAdd(&g_scandone, 1);
    }

    // ---- all blocks: wait for scan completion ----
    if (t == 0) {
        while (atomicAdd(&g_scandone, 0) < SCAN_BLOCKS) { }
    }
    __syncthreads();
    __threadfence();

    // ---- edge phase: full-precision alpha + CSR scatter ----
    int e = bid * 256 + t;        // EDGE_BLOCKS*256 == NE exactly
    int src = ei[e];
    int dst = ei[NE + e];
    float ev[7];
#pragma unroll
    for (int k = 0; k < 7; k++) ev[k] = ea[e * 7 + k];
    float4 ah4;
    float* ah = (float*)&ah4;
#pragma unroll
    for (int h = 0; h < 4; h++) {
        float s = 0.f;
#pragma unroll
        for (int k = 0; k < 7; k++) s = fmaf(ev[k], g_M[k * 4 + h], s);
        ah[h] = s;
    }
    red_add_v4(&g_aesum[dst * 4], ah4);
    float4 as = *(const float4*)&g_asrc[src * 4];
    float4 ad = *(const float4*)&g_adst[dst * 4];
    float4 a4;
    a4.x = lrelu(as.x + ad.x + ah[0]);
    a4.y = lrelu(as.y + ad.y + ah[1]);
    a4.z = lrelu(as.z + ad.z + ah[2]);
    a4.w = lrelu(as.w + ad.w + ah[3]);
    int pos = atomicAdd(&g_wptr[dst], 1);
    g_csrc[pos] = src;
    g_calpha[pos] = a4;
}

// ---------------- K3: one-pass softmax + aggregation, transposed weight computation ----------------
__global__ void k_agg(const float* __restrict__ bias) {
    int warp = (blockIdx.x * blockDim.x + threadIdx.x) >> 5;
    int lane = threadIdx.x & 31;
    if (warp >= N_NODES) return;
    int n = warp;
    int rs = g_rowptr[n], re = g_rowptr[n + 1];
    int deg = re - rs;

    // self-loop logit (same in every lane)
    float4 as4 = *(const float4*)&g_asrc[n * 4];
    float4 ad4 = *(const float4*)&g_adst[n * 4];
    float4 ae4 = *(const float4*)&g_aesum[n * 4];
    float invd = 1.0f / fmaxf((float)deg, 1.0f);
    float4 asl;
    asl.x = lrelu(as4.x + ad4.x + ae4.x * invd);
    asl.y = lrelu(as4.y + ad4.y + ae4.y * invd);
    asl.z = lrelu(as4.z + ad4.z + ae4.z * invd);
    asl.w = lrelu(as4.w + ad4.w + ae4.w * invd);

    int h = lane >> 3;
    int esub = lane & 7;
    float aslh = (h == 0) ? asl.x : (h == 1) ? asl.y : (h == 2) ? asl.z : asl.w;

    // seed with self-loop: weight exp(aslh - aslh) = 1
    float dh_tail = 1.0f;     // replicated within 8-lane group (do NOT reduce)
    float dh_chunk = 0.f;     // unique per (edge-slot, head) lane (reduce over group)
    float4 acc;
    {
        uint2 u = *(const uint2*)&g_xph[n * FF + lane * 4];
        float2 f01 = __half22float2(*(__half2*)&u.x);
        float2 f23 = __half22float2(*(__half2*)&u.y);
        acc = make_float4(f01.x, f01.y, f23.x, f23.y);
    }

    const float* abase = (const float*)g_calpha;
    int i = rs;
    for (; i + 8 <= re; i += 8) {
        // transposed weights: lane = (h, esub) computes exp for edge i+esub, head h
        float w_eh = __expf(abase[(i + esub) * 4 + h] - aslh);
        dh_chunk += w_eh;
        int s[8];
        uint2 u[8];
#pragma unroll
        for (int j = 0; j < 8; j++) s[j] = g_csrc[i + j];
#pragma unroll
        for (int j = 0; j < 8; j++) u[j] = *(const uint2*)&g_xph[s[j] * FF + lane * 4];
#pragma unroll
        for (int j = 0; j < 8; j++) {
            // weight for (edge i+j, my head) lives in lane h*8 + j
            float wgt = __shfl_sync(0xFFFFFFFFu, w_eh, (lane & 24) | j);
            float2 f01 = __half22float2(*(__half2*)&u[j].x);
            float2 f23 = __half22float2(*(__half2*)&u[j].y);
            acc.x += wgt * f01.x; acc.y += wgt * f01.y;
            acc.z += wgt * f23.x; acc.w += wgt * f23.y;
        }
    }
    for (; i < re; i++) {
        int s0 = g_csrc[i];
        float w0 = __expf(abase[i * 4 + h] - aslh);
        dh_tail += w0;
        uint2 u0 = *(const uint2*)&g_xph[s0 * FF + lane * 4];
        float2 a01 = __half22float2(*(__half2*)&u0.x), a23 = __half22float2(*(__half2*)&u0.y);
        acc.x += w0 * a01.x; acc.y += w0 * a01.y;
        acc.z += w0 * a23.x; acc.w += w0 * a23.y;
    }
    // reduce chunk denominators within each 8-lane head group
#pragma unroll
    for (int o = 1; o < 8; o <<= 1)
        dh_chunk += __shfl_xor_sync(0xFFFFFFFFu, dh_chunk, o);
    float ih = 1.0f / (dh_tail + dh_chunk);

    // ELU(out + bias)
    float4 b = *(const float4*)&bias[lane * 4];
    float r0 = acc.x * ih + b.x, r1 = acc.y * ih + b.y;
    float r2 = acc.z * ih + b.z, r3 = acc.w * ih + b.w;
    r0 = r0 > 0.f ? r0 : expm1f(r0);
    r1 = r1 > 0.f ? r1 : expm1f(r1);
    r2 = r2 > 0.f ? r2 : expm1f(r2);
    r3 = r3 > 0.f ? r3 : expm1f(r3);
    *(float4*)&g_h[n * FF + lane * 4] = make_float4(r0, r1, r2, r3);
}

// ---------------- K4: fused MLP via tf32 tensor cores ----------------
// smem: sW1[128][128] + sW2[128][32] + shA[64][132] + sh1[64][132]
#define MLP_SMEM (16384*4 + 4096*4 + 8448*4 + 8448*4)
__global__ void k_mlp(const float* __restrict__ W1, const float* __restrict__ b1,
                      const float* __restrict__ pa, const float* __restrict__ W2,
                      const float* __restrict__ b2, float* __restrict__ out) {
    extern __shared__ float smem[];
    float* sW1 = smem;              // [128][128]
    float* sW2 = sW1 + 16384;       // [128][32]
    float* shA = sW2 + 4096;        // [64][132]  input h (then layer-2 output)
    float* sh1 = shA + 8448;        // [64][132]  hidden h1
    int t = threadIdx.x;
    int w = t >> 5;
    int m0 = blockIdx.x * 64;

    for (int i = t; i < 16384; i += 256) sW1[i] = W1[i];
    for (int i = t; i < 4096; i += 256)  sW2[i] = W2[i];
    for (int i = t; i < 64 * 128; i += 256) {
        int r = i >> 7, k = i & 127;
        int node = m0 + r;
        shA[r * 132 + k] = (node < N_NODES) ? g_h[node * 128 + k] : 0.f;
    }
    float prelu = pa[0];
    __syncthreads();

    // ---- layer 1: [64x128] @ [128x128]; 8 warps, each a 32x32 tile ----
    {
        int wr = w >> 2, wc = w & 3;
        wm::fragment<wm::accumulator, 16, 16, 8, float> acc[2][2];
#pragma unroll
        for (int i = 0; i < 2; i++)
#pragma unroll
            for (int j = 0; j < 2; j++) wm::fill_fragment(acc[i][j], 0.f);
        for (int k = 0; k < 128; k += 8) {
            wm::fragment<wm::matrix_a, 16, 16, 8, wm::precision::tf32, wm::row_major> a[2];
            wm::fragment<wm::matrix_b, 16, 16, 8, wm::precision::tf32, wm::row_major> b[2];
#pragma unroll
            for (int i = 0; i < 2; i++) {
                wm::load_matrix_sync(a[i], &shA[(wr * 32 + i * 16) * 132 + k], 132);
#pragma unroll
                for (int e = 0; e < a[i].num_elements; e++) a[i].x[e] = wm::__float_to_tf32(a[i].x[e]);
            }
#pragma unroll
            for (int j = 0; j < 2; j++) {
                wm::load_matrix_sync(b[j], &sW1[k * 128 + wc * 32 + j * 16], 128);
#pragma unroll
                for (int e = 0; e < b[j].num_elements; e++) b[j].x[e] = wm::__float_to_tf32(b[j].x[e]);
            }
#pragma unroll
            for (int i = 0; i < 2; i++)
#pragma unroll
                for (int j = 0; j < 2; j++)
                    wm::mma_sync(acc[i][j], a[i], b[j], acc[i][j]);
        }
#pragma unroll
        for (int i = 0; i < 2; i++)
#pragma unroll
            for (int j = 0; j < 2; j++)
                wm::store_matrix_sync(&sh1[(wr * 32 + i * 16) * 132 + wc * 32 + j * 16],
                                      acc[i][j], 132, wm::mem_row_major);
    }
    __syncthreads();
    // bias + PReLU in place
    for (int i = t; i < 64 * 128; i += 256) {
        int r = i >> 7, c = i & 127;
        float v = sh1[r * 132 + c] + b1[c];
        sh1[r * 132 + c] = v > 0.f ? v : prelu * v;
    }
    __syncthreads();
    // ---- layer 2: [64x128] @ [128x32]; 8 warps, each one 16x16 tile ----
    {
        int wr = w >> 1, wc = w & 1;
        wm::fragment<wm::accumulator, 16, 16, 8, float> acc;
        wm::fill_fragment(acc, 0.f);
        for (int k = 0; k < 128; k += 8) {
            wm::fragment<wm::matrix_a, 16, 16, 8, wm::precision::tf32, wm::row_major> a;
            wm::fragment<wm::matrix_b, 16, 16, 8, wm::precision::tf32, wm::row_major> b;
            wm::load_matrix_sync(a, &sh1[(wr * 16) * 132 + k], 132);
#pragma unroll
            for (int e = 0; e < a.num_elements; e++) a.x[e] = wm::__float_to_tf32(a.x[e]);
            wm::load_matrix_sync(b, &sW2[k * 32 + wc * 16], 32);
#pragma unroll
            for (int e = 0; e < b.num_elements; e++) b.x[e] = wm::__float_to_tf32(b.x[e]);
            wm::mma_sync(acc, a, b, acc);
        }
        wm::store_matrix_sync(&shA[(wr * 16) * 132 + wc * 16], acc, 132, wm::mem_row_major);
    }
    __syncthreads();
    // write out with b2
    for (int i = t; i < 64 * 32; i += 256) {
        int r = i >> 5, c = i & 31;
        int node = m0 + r;
        if (node < N_NODES) out[node * 32 + c] = shA[r * 132 + c] + b2[c];
    }
}

// ---------------- launch ----------------
extern "C" void kernel_launch(void* const* d_in, const int* in_sizes, int n_in,
                              void* d_out, int out_size) {
    const float*     x        = (const float*)d_in[0];
    const int*       ei       = (const int*)d_in[1];
    const float*     ea       = (const float*)d_in[2];
    const float*     W_gat    = (const float*)d_in[3];
    const float*     att_src  = (const float*)d_in[4];
    const float*     att_dst  = (const float*)d_in[5];
    const float*     W_edge   = (const float*)d_in[6];
    const float*     att_edge = (const float*)d_in[7];
    const float*     bias_gat = (const float*)d_in[8];
    const float*     W1       = (const float*)d_in[9];
    const float*     b1       = (const float*)d_in[10];
    const float*     prelu_a  = (const float*)d_in[11];
    const float*     W2       = (const float*)d_in[12];
    const float*     b2       = (const float*)d_in[13];
    float*           out      = (float*)d_out;

    cudaFuncSetAttribute(k_mlp, cudaFuncAttributeMaxDynamicSharedMemorySize, MLP_SMEM);

    k_init<<<(N_NODES + 255) / 256, 256>>>(W_edge, att_edge);
    k_node_deg<<<NODE_BLOCKS + DEG_BLOCKS, 256>>>(x, W_gat, att_src, att_dst, ei);
    k_edge<<<EDGE_BLOCKS, 256>>>(ei, ea);
    k_agg<<<(N_NODES * 32 + 255) / 256, 256>>>(bias_gat);
    k_mlp<<<(N_NODES + 63) / 64, 256, MLP_SMEM>>>(W1, b1, prelu_a, W2, b2, out);
}